// round 12
// baseline (speedup 1.0000x reference)
#include <cuda_runtime.h>

#define Bx 16
#define NN 256
#define MM 256
#define DD 256
#define UU 256

typedef unsigned long long u64;

// scratch (device global — no allocations allowed)
__device__ float g_encpT[Bx * UU * MM];  // enc_proj TRANSPOSED [B][U][M]

__device__ __forceinline__ float tanh_ap(float x) {
    float y;
    asm("tanh.approx.f32 %0, %1;" : "=f"(y) : "f"(x));
    return y;
}
__device__ __forceinline__ u64 pk2(float lo, float hi) {
    u64 r;
    asm("mov.b64 %0, {%1, %2};" : "=l"(r) : "f"(lo), "f"(hi));
    return r;
}
__device__ __forceinline__ void upk2(u64 v, float& lo, float& hi) {
    asm("mov.b64 {%0, %1}, %2;" : "=f"(lo), "=f"(hi) : "l"(v));
}
__device__ __forceinline__ u64 ffma2(u64 a, u64 b, u64 c) {
    u64 d;
    asm("fma.rn.f32x2 %0, %1, %2, %3;" : "=l"(d) : "l"(a), "l"(b), "l"(c));
    return d;
}
__device__ __forceinline__ void cpa16(void* smem_dst, const void* gsrc) {
    unsigned sa = (unsigned)__cvta_generic_to_shared(smem_dst);
    asm volatile("cp.async.cg.shared.global [%0], [%1], 16;" :: "r"(sa), "l"(gsrc));
}
#define CPA_COMMIT asm volatile("cp.async.commit_group;")
#define CPA_WAIT1  asm volatile("cp.async.wait_group 1;")

// ---------------------------------------------------------------------------
// ENC-ONLY projection: enc@W1+b1 -> g_encpT (transposed [B,U,M]).
// 128x64 tile, 256 threads, 8x4 microtile, f32x2 FMA, double-buffered BK=16
// via LDG->regs->STS. Grid (4, 32) = 128 blocks.
// ---------------------------------------------------------------------------
__global__ __launch_bounds__(256) void proj_enc(const float* __restrict__ enc,
                                                const float* __restrict__ W1,
                                                const float* __restrict__ b1)
{
    __shared__ float As[2][16][136];   // k-major: [buf][k][r(128)+pad]
    __shared__ float Ws[2][16][64];    // [buf][k][c]

    const int tid = threadIdx.x;
    const int ty = tid >> 4;           // 0..15
    const int tx = tid & 15;           // 0..15
    const int row0 = blockIdx.y * 128;
    const int col0 = blockIdx.x * 64;

    const int r0l = (tid * 2) >> 2;
    const int kg0 = (tid * 2) & 3;
    const int r1l = (tid * 2 + 1) >> 2;
    const int kg1 = (tid * 2 + 1) & 3;
    const int kw = tid >> 4;
    const int cw = tid & 15;

    u64 acc[8][2] = {};

    float4 ra0 = *(const float4*)(enc + (size_t)(row0 + r0l) * 256 + kg0 * 4);
    float4 ra1 = *(const float4*)(enc + (size_t)(row0 + r1l) * 256 + kg1 * 4);
    float4 rw  = *(const float4*)(W1 + (size_t)kw * 256 + col0 + cw * 4);

    for (int t = 0; t < 16; t++) {
        const int bi = t & 1;
        As[bi][kg0 * 4 + 0][r0l] = ra0.x;
        As[bi][kg0 * 4 + 1][r0l] = ra0.y;
        As[bi][kg0 * 4 + 2][r0l] = ra0.z;
        As[bi][kg0 * 4 + 3][r0l] = ra0.w;
        As[bi][kg1 * 4 + 0][r1l] = ra1.x;
        As[bi][kg1 * 4 + 1][r1l] = ra1.y;
        As[bi][kg1 * 4 + 2][r1l] = ra1.z;
        As[bi][kg1 * 4 + 3][r1l] = ra1.w;
        *(float4*)&Ws[bi][kw][cw * 4] = rw;
        if (t + 1 < 16) {
            const int kt = (t + 1) * 16;
            ra0 = *(const float4*)(enc + (size_t)(row0 + r0l) * 256 + kt + kg0 * 4);
            ra1 = *(const float4*)(enc + (size_t)(row0 + r1l) * 256 + kt + kg1 * 4);
            rw  = *(const float4*)(W1 + (size_t)(kt + kw) * 256 + col0 + cw * 4);
        }
        __syncthreads();
        #pragma unroll
        for (int k = 0; k < 16; k++) {
            float4 aA = *(const float4*)&As[bi][k][ty * 4];
            float4 aB = *(const float4*)&As[bi][k][64 + ty * 4];
            float4 w  = *(const float4*)&Ws[bi][k][tx * 4];
            u64 w01 = pk2(w.x, w.y);
            u64 w23 = pk2(w.z, w.w);
            float av[8] = {aA.x, aA.y, aA.z, aA.w, aB.x, aB.y, aB.z, aB.w};
            #pragma unroll
            for (int ri = 0; ri < 8; ri++) {
                u64 aa = pk2(av[ri], av[ri]);
                acc[ri][0] = ffma2(aa, w01, acc[ri][0]);
                acc[ri][1] = ffma2(aa, w23, acc[ri][1]);
            }
        }
        __syncthreads();
    }

    float c[8][4];
    #pragma unroll
    for (int ri = 0; ri < 8; ri++) {
        upk2(acc[ri][0], c[ri][0], c[ri][1]);
        upk2(acc[ri][1], c[ri][2], c[ri][3]);
    }
    float4 bv = *(const float4*)(b1 + col0 + tx * 4);
    float bb[4] = {bv.x, bv.y, bv.z, bv.w};

    const int b  = row0 >> 8;
    const int m0 = row0 & 255;
    const int mA = m0 + ty * 4;
    const int mB = m0 + 64 + ty * 4;
    #pragma unroll
    for (int cj = 0; cj < 4; cj++) {
        int u = col0 + tx * 4 + cj;
        float bbv = bb[cj];
        float4 vA, vB;
        vA.x = c[0][cj] + bbv; vA.y = c[1][cj] + bbv;
        vA.z = c[2][cj] + bbv; vA.w = c[3][cj] + bbv;
        vB.x = c[4][cj] + bbv; vB.y = c[5][cj] + bbv;
        vB.z = c[6][cj] + bbv; vB.w = c[7][cj] + bbv;
        *(float4*)(g_encpT + (size_t)b * 65536 + (size_t)u * 256 + mA) = vA;
        *(float4*)(g_encpT + (size_t)b * 65536 + (size_t)u * 256 + mB) = vB;
    }
}

// ---------------------------------------------------------------------------
// Fused attention (R7 structure, measured 86.6us) + integrated dec projection:
// each block computes its own 8 dec_proj rows (8x256x256 mini-GEMM through
// the sB cp.async buffers, outputs straight to sD) — no g_decp, and the
// standalone proj kernel only does enc now.
// Block = 8 n-rows of one b, 512 blocks, 256 threads = 8 warps.
// ---------------------------------------------------------------------------
__global__ __launch_bounds__(256, 4) void attn_kernel(const float* __restrict__ enc,
                                                      const float* __restrict__ dec,
                                                      const float* __restrict__ W2,
                                                      const float* __restrict__ b2,
                                                      const float* __restrict__ v_w,
                                                      float* __restrict__ out_ctx,
                                                      float* __restrict__ out_w)
{
    __shared__ float4 sB[2][1024];    // 2 x 16KB staging
    __shared__ float sD[8 * 256];     // dec_proj rows (computed in preamble)
    __shared__ float sW[8 * 256];     // dec input (preamble) -> softmax weights
    __shared__ float sV[256];         // v_w
    float* sP = (float*)sB[1];        // alias: partial-exchange buffer (buf1)

    const int tid  = threadIdx.x;
    const int warp = tid >> 5;
    const int lane = tid & 31;
    const int h    = warp >> 2;       // 0: axis [0,128)   1: axis [128,256)
    const int wl   = warp & 3;
    const int r0   = wl * 2;
    const int r1   = r0 + 1;

    const int b  = blockIdx.x >> 5;
    const int n0 = (blockIdx.x & 31) * 8;
    const int gn0 = n0 + r0;
    const int gn1 = n0 + r1;

    const int pr = tid >> 6;          // prefetch row-group base (0..3)
    const int pc = tid & 63;          // prefetch col

    // ---- preamble: dec_proj rows n0..n0+7 = dec[8,256] @ W2[256,256] + b2 --
    {
        // stage v and the 8 dec input rows (into sW as temp)
        float4* sV4 = (float4*)sV;
        if (tid < 64) sV4[tid] = ((const float4*)v_w)[tid];
        const float4* dsrc = (const float4*)(dec + (size_t)(b * NN + n0) * DD);
        float4* sWtmp = (float4*)sW;
        sWtmp[tid]       = dsrc[tid];
        sWtmp[tid + 256] = dsrc[tid + 256];

        const float4* w2_4 = (const float4*)W2;
        const int dr  = tid >> 5;     // output row 0..7
        const int dc  = tid & 31;     // col group: cols dc*4.. and 128+dc*4..

        #define PREF_W2(s, bi)                                                 \
            {                                                                  \
                _Pragma("unroll")                                              \
                for (int q = 0; q < 4; q++) {                                  \
                    int fid = tid * 4 + q;                                     \
                    int r = fid >> 6;                                          \
                    int c = fid & 63;                                          \
                    cpa16(&sB[bi][r * 64 + c],                                 \
                          w2_4 + (size_t)((s) * 16 + r) * 64 + c);             \
                }                                                              \
            }

        PREF_W2(0, 0);
        CPA_COMMIT;
        __syncthreads();   // dec rows in sW visible

        u64 accL[2] = {0, 0};
        u64 accH[2] = {0, 0};
        for (int s = 0; s < 16; s++) {
            if (s + 1 < 16) PREF_W2(s + 1, (s + 1) & 1);
            CPA_COMMIT;
            CPA_WAIT1;
            __syncthreads();
            const float4* buf = sB[s & 1];
            #pragma unroll
            for (int k = 0; k < 16; k++) {
                float dv = sW[dr * 256 + s * 16 + k];
                u64 dd = pk2(dv, dv);
                float4 wL = buf[k * 64 + dc];
                float4 wH = buf[k * 64 + 32 + dc];
                accL[0] = ffma2(dd, pk2(wL.x, wL.y), accL[0]);
                accL[1] = ffma2(dd, pk2(wL.z, wL.w), accL[1]);
                accH[0] = ffma2(dd, pk2(wH.x, wH.y), accH[0]);
                accH[1] = ffma2(dd, pk2(wH.z, wH.w), accH[1]);
            }
            __syncthreads();
        }
        #undef PREF_W2

        float4 oL, oH;
        upk2(accL[0], oL.x, oL.y); upk2(accL[1], oL.z, oL.w);
        upk2(accH[0], oH.x, oH.y); upk2(accH[1], oH.z, oH.w);
        float4 bL = ((const float4*)b2)[dc];
        float4 bH = ((const float4*)b2)[32 + dc];
        oL.x += bL.x; oL.y += bL.y; oL.z += bL.z; oL.w += bL.w;
        oH.x += bH.x; oH.y += bH.y; oH.z += bH.z; oH.w += bH.w;
        ((float4*)(sD + dr * 256))[dc]      = oL;
        ((float4*)(sD + dr * 256))[32 + dc] = oH;
        __syncthreads();
    }

    const float4* eb4 = (const float4*)(g_encpT + (size_t)b * 65536);
    const float4* en4 = (const float4*)(enc + (size_t)b * 65536);

    // chunk s covers rows r=0..15: r<8 -> u=s*8+r (low half); r>=8 -> u=128+s*8+(r-8)
    #define PREFETCH(src, s, buf)                                              \
        {                                                                      \
            _Pragma("unroll")                                                  \
            for (int t = 0; t < 4; t++) {                                      \
                int r = pr + t * 4;                                            \
                int u = (s) * 8 + r + ((r < 8) ? 0 : 120);                     \
                cpa16((buf) + r * 64 + pc, (src) + u * 64 + pc);               \
            }                                                                  \
        }

    // ---- phase 1: logits (u split across warp halves) ----
    float lg0[8] = {0,0,0,0,0,0,0,0};
    float lg1[8] = {0,0,0,0,0,0,0,0};
    {
        const float* dRow0 = sD + r0 * 256 + h * 128;
        const float* dRow1 = sD + r1 * 256 + h * 128;
        const float* vHalf = sV + h * 128;

        PREFETCH(eb4, 0, sB[0]);
        CPA_COMMIT;
        for (int s = 0; s < 16; s++) {
            if (s + 1 < 16) PREFETCH(eb4, s + 1, sB[(s + 1) & 1]);
            CPA_COMMIT;
            CPA_WAIT1;
            __syncthreads();
            const float4* buf = sB[s & 1];
            #pragma unroll
            for (int j = 0; j < 8; j++) {
                const int ul = s * 8 + j;
                const float dn0 = dRow0[ul];
                const float dn1 = dRow1[ul];
                const float vu  = vHalf[ul];
                float4 ea = buf[(h * 8 + j) * 64 + lane];
                float4 eb = buf[(h * 8 + j) * 64 + 32 + lane];
                lg0[0] = fmaf(vu, tanh_ap(ea.x + dn0), lg0[0]);
                lg0[1] = fmaf(vu, tanh_ap(ea.y + dn0), lg0[1]);
                lg0[2] = fmaf(vu, tanh_ap(ea.z + dn0), lg0[2]);
                lg0[3] = fmaf(vu, tanh_ap(ea.w + dn0), lg0[3]);
                lg0[4] = fmaf(vu, tanh_ap(eb.x + dn0), lg0[4]);
                lg0[5] = fmaf(vu, tanh_ap(eb.y + dn0), lg0[5]);
                lg0[6] = fmaf(vu, tanh_ap(eb.z + dn0), lg0[6]);
                lg0[7] = fmaf(vu, tanh_ap(eb.w + dn0), lg0[7]);
                lg1[0] = fmaf(vu, tanh_ap(ea.x + dn1), lg1[0]);
                lg1[1] = fmaf(vu, tanh_ap(ea.y + dn1), lg1[1]);
                lg1[2] = fmaf(vu, tanh_ap(ea.z + dn1), lg1[2]);
                lg1[3] = fmaf(vu, tanh_ap(ea.w + dn1), lg1[3]);
                lg1[4] = fmaf(vu, tanh_ap(eb.x + dn1), lg1[4]);
                lg1[5] = fmaf(vu, tanh_ap(eb.y + dn1), lg1[5]);
                lg1[6] = fmaf(vu, tanh_ap(eb.z + dn1), lg1[6]);
                lg1[7] = fmaf(vu, tanh_ap(eb.w + dn1), lg1[7]);
            }
            __syncthreads();
        }
    }

    // overlap: stream phase-3 chunk 0 into buf0 while exchanging in buf1 (=sP)
    PREFETCH(en4, 0, sB[0]);
    CPA_COMMIT;

    // ---- exchange u-partials, softmax (low warps), write weights ----
    if (h == 1) {
        float4* p0 = (float4*)(sP + r0 * 256);
        float4* p1 = (float4*)(sP + r1 * 256);
        p0[lane]      = make_float4(lg0[0], lg0[1], lg0[2], lg0[3]);
        p0[32 + lane] = make_float4(lg0[4], lg0[5], lg0[6], lg0[7]);
        p1[lane]      = make_float4(lg1[0], lg1[1], lg1[2], lg1[3]);
        p1[32 + lane] = make_float4(lg1[4], lg1[5], lg1[6], lg1[7]);
    }
    __syncthreads();
    if (h == 0) {
        {
            float4 q;
            q = ((float4*)(sP + r0 * 256))[lane];
            lg0[0] += q.x; lg0[1] += q.y; lg0[2] += q.z; lg0[3] += q.w;
            q = ((float4*)(sP + r0 * 256))[32 + lane];
            lg0[4] += q.x; lg0[5] += q.y; lg0[6] += q.z; lg0[7] += q.w;
            q = ((float4*)(sP + r1 * 256))[lane];
            lg1[0] += q.x; lg1[1] += q.y; lg1[2] += q.z; lg1[3] += q.w;
            q = ((float4*)(sP + r1 * 256))[32 + lane];
            lg1[4] += q.x; lg1[5] += q.y; lg1[6] += q.z; lg1[7] += q.w;
        }
        #pragma unroll
        for (int r = 0; r < 2; r++) {
            float* lg = r ? lg1 : lg0;
            const int ln = r ? r1 : r0;
            const int gn = n0 + ln;
            float mx = lg[0];
            #pragma unroll
            for (int k = 1; k < 8; k++) mx = fmaxf(mx, lg[k]);
            #pragma unroll
            for (int o = 16; o > 0; o >>= 1) mx = fmaxf(mx, __shfl_xor_sync(0xFFFFFFFFu, mx, o));
            float sum = 0.f;
            #pragma unroll
            for (int k = 0; k < 8; k++) { lg[k] = __expf(lg[k] - mx); sum += lg[k]; }
            #pragma unroll
            for (int o = 16; o > 0; o >>= 1) sum += __shfl_xor_sync(0xFFFFFFFFu, sum, o);
            const float inv = 1.f / sum;

            float4 wA, wB;
            wA.x = lg[0] * inv; wA.y = lg[1] * inv; wA.z = lg[2] * inv; wA.w = lg[3] * inv;
            wB.x = lg[4] * inv; wB.y = lg[5] * inv; wB.z = lg[6] * inv; wB.w = lg[7] * inv;
            ((float4*)(sW + ln * 256))[lane]      = wA;
            ((float4*)(sW + ln * 256))[32 + lane] = wB;
            float4* wo = (float4*)(out_w + (size_t)(b * NN + gn) * MM);
            wo[lane]      = wA;
            wo[32 + lane] = wB;
        }
    }
    __syncthreads();

    // ---- phase 3: context (m split across halves; f32x2 FMA; lanes span d) --
    u64 c0[4] = {0, 0, 0, 0};
    u64 c1[4] = {0, 0, 0, 0};
    {
        const float* w0p = sW + r0 * 256 + h * 128;
        const float* w1p = sW + r1 * 256 + h * 128;

        for (int s = 0; s < 16; s++) {
            if (s + 1 < 16) PREFETCH(en4, s + 1, sB[(s + 1) & 1]);
            CPA_COMMIT;
            CPA_WAIT1;
            __syncthreads();
            const float4* buf = sB[s & 1];
            #pragma unroll
            for (int j = 0; j < 8; j++) {
                const float w0 = w0p[s * 8 + j];
                const float w1 = w1p[s * 8 + j];
                u64 ww0 = pk2(w0, w0);
                u64 ww1 = pk2(w1, w1);
                float4 ea = buf[(h * 8 + j) * 64 + lane];
                float4 eb = buf[(h * 8 + j) * 64 + 32 + lane];
                u64 e0 = pk2(ea.x, ea.y);
                u64 e1 = pk2(ea.z, ea.w);
                u64 e2 = pk2(eb.x, eb.y);
                u64 e3 = pk2(eb.z, eb.w);
                c0[0] = ffma2(ww0, e0, c0[0]);
                c0[1] = ffma2(ww0, e1, c0[1]);
                c0[2] = ffma2(ww0, e2, c0[2]);
                c0[3] = ffma2(ww0, e3, c0[3]);
                c1[0] = ffma2(ww1, e0, c1[0]);
                c1[1] = ffma2(ww1, e1, c1[1]);
                c1[2] = ffma2(ww1, e2, c1[2]);
                c1[3] = ffma2(ww1, e3, c1[3]);
            }
            __syncthreads();
        }
    }

    // ---- exchange m-partials, store context ----
    float4 c0a, c0b, c1a, c1b;
    upk2(c0[0], c0a.x, c0a.y); upk2(c0[1], c0a.z, c0a.w);
    upk2(c0[2], c0b.x, c0b.y); upk2(c0[3], c0b.z, c0b.w);
    upk2(c1[0], c1a.x, c1a.y); upk2(c1[1], c1a.z, c1a.w);
    upk2(c1[2], c1b.x, c1b.y); upk2(c1[3], c1b.z, c1b.w);

    if (h == 1) {
        float4* p0 = (float4*)(sP + r0 * 256);
        float4* p1 = (float4*)(sP + r1 * 256);
        p0[lane]      = c0a;
        p0[32 + lane] = c0b;
        p1[lane]      = c1a;
        p1[32 + lane] = c1b;
    }
    __syncthreads();
    if (h == 0) {
        float4 q;
        q = ((float4*)(sP + r0 * 256))[lane];
        c0a.x += q.x; c0a.y += q.y; c0a.z += q.z; c0a.w += q.w;
        q = ((float4*)(sP + r0 * 256))[32 + lane];
        c0b.x += q.x; c0b.y += q.y; c0b.z += q.z; c0b.w += q.w;
        q = ((float4*)(sP + r1 * 256))[lane];
        c1a.x += q.x; c1a.y += q.y; c1a.z += q.z; c1a.w += q.w;
        q = ((float4*)(sP + r1 * 256))[32 + lane];
        c1b.x += q.x; c1b.y += q.y; c1b.z += q.z; c1b.w += q.w;

        float4* o0 = (float4*)(out_ctx + (size_t)(b * NN + gn0) * DD);
        o0[lane]      = c0a;
        o0[32 + lane] = c0b;
        float4* o1 = (float4*)(out_ctx + (size_t)(b * NN + gn1) * DD);
        o1[lane]      = c1a;
        o1[32 + lane] = c1b;
    }
    #undef PREFETCH
}

extern "C" void kernel_launch(void* const* d_in, const int* in_sizes, int n_in,
                              void* d_out, int out_size)
{
    const float* enc = (const float*)d_in[0];
    const float* dec = (const float*)d_in[1];
    const float* W1  = (const float*)d_in[2];
    const float* b1  = (const float*)d_in[3];
    const float* W2  = (const float*)d_in[4];
    const float* b2  = (const float*)d_in[5];
    const float* vw  = (const float*)d_in[6];
    // d_in[7] = v_b: constant shift, cancels in softmax -> unused.

    float* out_ctx = (float*)d_out;                              // [B,N,D]
    float* out_w   = (float*)d_out + (size_t)Bx * NN * DD;       // [B,N,M,1]

    proj_enc<<<dim3(4, 32), 256>>>(enc, W1, b1);
    attn_kernel<<<512, 256>>>(enc, dec, W2, b2, vw, out_ctx, out_w);
}

// round 13
// speedup vs baseline: 1.1435x; 1.1435x over previous
#include <cuda_runtime.h>

#define Bx 16
#define NN 256
#define MM 256
#define DD 256
#define UU 256

typedef unsigned long long u64;

// scratch (device globals — no allocations allowed)
__device__ float g_encpT[Bx * UU * MM];  // enc_proj TRANSPOSED [B][U][M]
__device__ float g_decp [Bx * NN * UU];  // dec_proj [B][N][U]

__device__ __forceinline__ float tanh_ap(float x) {
    float y;
    asm("tanh.approx.f32 %0, %1;" : "=f"(y) : "f"(x));
    return y;
}
__device__ __forceinline__ u64 pk2(float lo, float hi) {
    u64 r;
    asm("mov.b64 %0, {%1, %2};" : "=l"(r) : "f"(lo), "f"(hi));
    return r;
}
__device__ __forceinline__ void upk2(u64 v, float& lo, float& hi) {
    asm("mov.b64 {%0, %1}, %2;" : "=f"(lo), "=f"(hi) : "l"(v));
}
__device__ __forceinline__ u64 ffma2(u64 a, u64 b, u64 c) {
    u64 d;
    asm("fma.rn.f32x2 %0, %1, %2, %3;" : "=l"(d) : "l"(a), "l"(b), "l"(c));
    return d;
}
__device__ __forceinline__ void cpa16(void* smem_dst, const void* gsrc) {
    unsigned sa = (unsigned)__cvta_generic_to_shared(smem_dst);
    asm volatile("cp.async.cg.shared.global [%0], [%1], 16;" :: "r"(sa), "l"(gsrc));
}
#define CPA_COMMIT asm volatile("cp.async.commit_group;")
#define CPA_WAIT1  asm volatile("cp.async.wait_group 1;")

// ---------------------------------------------------------------------------
// Projection GEMM (R7 version — proven): 128x128 tile, 256 threads, 8x8
// microtile, f32x2 FMA, cp.async double-buffered BK=16. Grid (2,32,2).
// z=0: enc@W1+b1 -> g_encpT (transposed [B,U,M]); z=1: dec@W2+b2 -> g_decp.
// ---------------------------------------------------------------------------
__global__ __launch_bounds__(256) void proj_gemm(const float* __restrict__ enc,
                                                 const float* __restrict__ dec,
                                                 const float* __restrict__ W1,
                                                 const float* __restrict__ b1,
                                                 const float* __restrict__ W2,
                                                 const float* __restrict__ b2)
{
    const int z = blockIdx.z;
    const float* A    = z ? dec : enc;
    const float* W    = z ? W2  : W1;
    const float* bias = z ? b2  : b1;

    __shared__ float As[2][128 * 20];
    __shared__ float Ws[2][16 * 128];

    const int tid = threadIdx.x;
    const int ty = tid >> 4;
    const int tx = tid & 15;
    const int row0 = blockIdx.y * 128;
    const int col0 = blockIdx.x * 128;

    u64 acc[8][4] = {};

    #define PROJ_PREF(kt, bi)                                                   \
        {                                                                       \
            _Pragma("unroll")                                                   \
            for (int i = 0; i < 2; i++) {                                       \
                int fid = tid * 2 + i;                                          \
                int r = fid >> 2, kg = fid & 3;                                 \
                cpa16(&As[bi][r * 20 + kg * 4],                                 \
                      A + (size_t)(row0 + r) * 256 + (kt) + kg * 4);            \
            }                                                                   \
            _Pragma("unroll")                                                   \
            for (int i = 0; i < 2; i++) {                                       \
                int fid = tid * 2 + i;                                          \
                int k = fid >> 5, c4 = fid & 31;                                \
                cpa16(&Ws[bi][k * 128 + c4 * 4],                                \
                      W + (size_t)((kt) + k) * 256 + col0 + c4 * 4);            \
            }                                                                   \
        }

    PROJ_PREF(0, 0);
    CPA_COMMIT;
    for (int t16 = 0; t16 < 16; t16++) {
        if (t16 + 1 < 16) PROJ_PREF((t16 + 1) * 16, (t16 + 1) & 1);
        CPA_COMMIT;
        CPA_WAIT1;
        __syncthreads();
        const float* as = As[t16 & 1];
        const float* ws = Ws[t16 & 1];
        #pragma unroll
        for (int k = 0; k < 16; k++) {
            float4 wlo = *(const float4*)(ws + k * 128 + tx * 4);
            float4 whi = *(const float4*)(ws + k * 128 + 64 + tx * 4);
            u64 w0 = pk2(wlo.x, wlo.y);
            u64 w1 = pk2(wlo.z, wlo.w);
            u64 w2 = pk2(whi.x, whi.y);
            u64 w3 = pk2(whi.z, whi.w);
            #pragma unroll
            for (int ri = 0; ri < 8; ri++) {
                int r = (ri < 4) ? (ty * 4 + ri) : (64 + ty * 4 + ri - 4);
                float av = as[r * 20 + k];
                u64 aa = pk2(av, av);
                acc[ri][0] = ffma2(aa, w0, acc[ri][0]);
                acc[ri][1] = ffma2(aa, w1, acc[ri][1]);
                acc[ri][2] = ffma2(aa, w2, acc[ri][2]);
                acc[ri][3] = ffma2(aa, w3, acc[ri][3]);
            }
        }
        __syncthreads();
    }
    #undef PROJ_PREF

    float c[8][8];
    #pragma unroll
    for (int ri = 0; ri < 8; ri++) {
        upk2(acc[ri][0], c[ri][0], c[ri][1]);
        upk2(acc[ri][1], c[ri][2], c[ri][3]);
        upk2(acc[ri][2], c[ri][4], c[ri][5]);
        upk2(acc[ri][3], c[ri][6], c[ri][7]);
    }
    float4 bl = *(const float4*)(bias + col0 + tx * 4);
    float4 bh = *(const float4*)(bias + col0 + 64 + tx * 4);
    float bb[8] = {bl.x, bl.y, bl.z, bl.w, bh.x, bh.y, bh.z, bh.w};

    if (z) {
        #pragma unroll
        for (int ri = 0; ri < 8; ri++) {
            int gr = row0 + ((ri < 4) ? (ty * 4 + ri) : (64 + ty * 4 + ri - 4));
            float4 lo, hi;
            lo.x = c[ri][0] + bb[0]; lo.y = c[ri][1] + bb[1];
            lo.z = c[ri][2] + bb[2]; lo.w = c[ri][3] + bb[3];
            hi.x = c[ri][4] + bb[4]; hi.y = c[ri][5] + bb[5];
            hi.z = c[ri][6] + bb[6]; hi.w = c[ri][7] + bb[7];
            *(float4*)(g_decp + (size_t)gr * 256 + col0 + tx * 4) = lo;
            *(float4*)(g_decp + (size_t)gr * 256 + col0 + 64 + tx * 4) = hi;
        }
    } else {
        const int b  = row0 >> 8;
        const int m0 = row0 & 255;
        const int mA = m0 + ty * 4;
        const int mB = m0 + 64 + ty * 4;
        #pragma unroll
        for (int cj = 0; cj < 8; cj++) {
            int u = col0 + ((cj < 4) ? (tx * 4 + cj) : (64 + tx * 4 + cj - 4));
            float bbv = bb[cj];
            float4 vA, vB;
            vA.x = c[0][cj] + bbv; vA.y = c[1][cj] + bbv;
            vA.z = c[2][cj] + bbv; vA.w = c[3][cj] + bbv;
            vB.x = c[4][cj] + bbv; vB.y = c[5][cj] + bbv;
            vB.z = c[6][cj] + bbv; vB.w = c[7][cj] + bbv;
            *(float4*)(g_encpT + (size_t)b * 65536 + (size_t)u * 256 + mA) = vA;
            *(float4*)(g_encpT + (size_t)b * 65536 + (size_t)u * 256 + mB) = vB;
        }
    }
}

// ---------------------------------------------------------------------------
// Fused attention. Phase 1 + softmax: R7 VERBATIM (measured 86.6us, near
// tanh-XU floor). Phase 3 changed to register-direct LDG: no smem staging,
// no barriers; 8 independent f32x2 chains per thread; 4 warps/half read the
// same L1 lines. Accumulation order over m identical to R7.
// Block = 8 n-rows of one b, 512 blocks, 256 threads = 8 warps.
// ---------------------------------------------------------------------------
__global__ __launch_bounds__(256, 4) void attn_kernel(const float* __restrict__ enc,
                                                      const float* __restrict__ v_w,
                                                      float* __restrict__ out_ctx,
                                                      float* __restrict__ out_w)
{
    __shared__ float4 sB[2][1024];    // 2 x 16KB staging (phase 1 only)
    __shared__ float sD[8 * 256];     // dec_proj rows (8KB)
    __shared__ float sW[8 * 256];     // softmax weights (8KB)
    __shared__ float sV[256];         // v_w (1KB)
    float* sP = (float*)sB[1];        // alias: partial-exchange buffer (buf1)

    const int tid  = threadIdx.x;
    const int warp = tid >> 5;
    const int lane = tid & 31;
    const int h    = warp >> 2;       // 0: axis [0,128)   1: axis [128,256)
    const int wl   = warp & 3;
    const int r0   = wl * 2;
    const int r1   = r0 + 1;

    const int b  = blockIdx.x >> 5;
    const int n0 = (blockIdx.x & 31) * 8;
    const int gn0 = n0 + r0;
    const int gn1 = n0 + r1;

    const int pr = tid >> 6;          // prefetch row-group base (0..3)
    const int pc = tid & 63;          // prefetch col

    // stage v and dec_proj tile
    {
        float4* sV4 = (float4*)sV;
        if (tid < 64) sV4[tid] = ((const float4*)v_w)[tid];
        const float4* dsrc = (const float4*)(g_decp + (size_t)(b * NN + n0) * UU);
        float4* sD4 = (float4*)sD;
        sD4[tid] = dsrc[tid];
        sD4[tid + 256] = dsrc[tid + 256];
    }

    const float4* eb4 = (const float4*)(g_encpT + (size_t)b * 65536);
    const float4* en4 = (const float4*)(enc + (size_t)b * 65536);

    // chunk s covers rows r=0..15: r<8 -> u=s*8+r (low half); r>=8 -> u=128+s*8+(r-8)
    #define PREFETCH(src, s, buf)                                              \
        {                                                                      \
            _Pragma("unroll")                                                  \
            for (int t = 0; t < 4; t++) {                                      \
                int r = pr + t * 4;                                            \
                int u = (s) * 8 + r + ((r < 8) ? 0 : 120);                     \
                cpa16((buf) + r * 64 + pc, (src) + u * 64 + pc);               \
            }                                                                  \
        }

    // ---- phase 1: logits (u split across warp halves) ----
    float lg0[8] = {0,0,0,0,0,0,0,0};
    float lg1[8] = {0,0,0,0,0,0,0,0};
    {
        const float* dRow0 = sD + r0 * 256 + h * 128;
        const float* dRow1 = sD + r1 * 256 + h * 128;
        const float* vHalf = sV + h * 128;

        PREFETCH(eb4, 0, sB[0]);
        CPA_COMMIT;
        for (int s = 0; s < 16; s++) {
            if (s + 1 < 16) PREFETCH(eb4, s + 1, sB[(s + 1) & 1]);
            CPA_COMMIT;
            CPA_WAIT1;
            __syncthreads();
            const float4* buf = sB[s & 1];
            #pragma unroll
            for (int j = 0; j < 8; j++) {
                const int ul = s * 8 + j;
                const float dn0 = dRow0[ul];
                const float dn1 = dRow1[ul];
                const float vu  = vHalf[ul];
                float4 ea = buf[(h * 8 + j) * 64 + lane];
                float4 eb = buf[(h * 8 + j) * 64 + 32 + lane];
                lg0[0] = fmaf(vu, tanh_ap(ea.x + dn0), lg0[0]);
                lg0[1] = fmaf(vu, tanh_ap(ea.y + dn0), lg0[1]);
                lg0[2] = fmaf(vu, tanh_ap(ea.z + dn0), lg0[2]);
                lg0[3] = fmaf(vu, tanh_ap(ea.w + dn0), lg0[3]);
                lg0[4] = fmaf(vu, tanh_ap(eb.x + dn0), lg0[4]);
                lg0[5] = fmaf(vu, tanh_ap(eb.y + dn0), lg0[5]);
                lg0[6] = fmaf(vu, tanh_ap(eb.z + dn0), lg0[6]);
                lg0[7] = fmaf(vu, tanh_ap(eb.w + dn0), lg0[7]);
                lg1[0] = fmaf(vu, tanh_ap(ea.x + dn1), lg1[0]);
                lg1[1] = fmaf(vu, tanh_ap(ea.y + dn1), lg1[1]);
                lg1[2] = fmaf(vu, tanh_ap(ea.z + dn1), lg1[2]);
                lg1[3] = fmaf(vu, tanh_ap(ea.w + dn1), lg1[3]);
                lg1[4] = fmaf(vu, tanh_ap(eb.x + dn1), lg1[4]);
                lg1[5] = fmaf(vu, tanh_ap(eb.y + dn1), lg1[5]);
                lg1[6] = fmaf(vu, tanh_ap(eb.z + dn1), lg1[6]);
                lg1[7] = fmaf(vu, tanh_ap(eb.w + dn1), lg1[7]);
            }
            __syncthreads();
        }
    }

    // ---- exchange u-partials, softmax (low warps), write weights ----
    if (h == 1) {
        float4* p0 = (float4*)(sP + r0 * 256);
        float4* p1 = (float4*)(sP + r1 * 256);
        p0[lane]      = make_float4(lg0[0], lg0[1], lg0[2], lg0[3]);
        p0[32 + lane] = make_float4(lg0[4], lg0[5], lg0[6], lg0[7]);
        p1[lane]      = make_float4(lg1[0], lg1[1], lg1[2], lg1[3]);
        p1[32 + lane] = make_float4(lg1[4], lg1[5], lg1[6], lg1[7]);
    }
    __syncthreads();
    if (h == 0) {
        {
            float4 q;
            q = ((float4*)(sP + r0 * 256))[lane];
            lg0[0] += q.x; lg0[1] += q.y; lg0[2] += q.z; lg0[3] += q.w;
            q = ((float4*)(sP + r0 * 256))[32 + lane];
            lg0[4] += q.x; lg0[5] += q.y; lg0[6] += q.z; lg0[7] += q.w;
            q = ((float4*)(sP + r1 * 256))[lane];
            lg1[0] += q.x; lg1[1] += q.y; lg1[2] += q.z; lg1[3] += q.w;
            q = ((float4*)(sP + r1 * 256))[32 + lane];
            lg1[4] += q.x; lg1[5] += q.y; lg1[6] += q.z; lg1[7] += q.w;
        }
        #pragma unroll
        for (int r = 0; r < 2; r++) {
            float* lg = r ? lg1 : lg0;
            const int ln = r ? r1 : r0;
            const int gn = n0 + ln;
            float mx = lg[0];
            #pragma unroll
            for (int k = 1; k < 8; k++) mx = fmaxf(mx, lg[k]);
            #pragma unroll
            for (int o = 16; o > 0; o >>= 1) mx = fmaxf(mx, __shfl_xor_sync(0xFFFFFFFFu, mx, o));
            float sum = 0.f;
            #pragma unroll
            for (int k = 0; k < 8; k++) { lg[k] = __expf(lg[k] - mx); sum += lg[k]; }
            #pragma unroll
            for (int o = 16; o > 0; o >>= 1) sum += __shfl_xor_sync(0xFFFFFFFFu, sum, o);
            const float inv = 1.f / sum;

            float4 wA, wB;
            wA.x = lg[0] * inv; wA.y = lg[1] * inv; wA.z = lg[2] * inv; wA.w = lg[3] * inv;
            wB.x = lg[4] * inv; wB.y = lg[5] * inv; wB.z = lg[6] * inv; wB.w = lg[7] * inv;
            ((float4*)(sW + ln * 256))[lane]      = wA;
            ((float4*)(sW + ln * 256))[32 + lane] = wB;
            float4* wo = (float4*)(out_w + (size_t)(b * NN + gn) * MM);
            wo[lane]      = wA;
            wo[32 + lane] = wB;
        }
    }
    __syncthreads();

    // ---- phase 3: context — register-direct LDG, no barriers ----
    // warp covers m in [h*128, h*128+128), rows r0/r1; lanes span d.
    u64 c0[4] = {0, 0, 0, 0};
    u64 c1[4] = {0, 0, 0, 0};
    {
        const float* w0p = sW + r0 * 256 + h * 128;
        const float* w1p = sW + r1 * 256 + h * 128;
        const float4* ep = en4 + (size_t)(h * 128) * 64;

        #pragma unroll 4
        for (int mi = 0; mi < 128; mi++) {
            float4 ea = ep[mi * 64 + lane];
            float4 eb = ep[mi * 64 + 32 + lane];
            const float w0 = w0p[mi];
            const float w1 = w1p[mi];
            u64 ww0 = pk2(w0, w0);
            u64 ww1 = pk2(w1, w1);
            u64 e0 = pk2(ea.x, ea.y);
            u64 e1 = pk2(ea.z, ea.w);
            u64 e2 = pk2(eb.x, eb.y);
            u64 e3 = pk2(eb.z, eb.w);
            c0[0] = ffma2(ww0, e0, c0[0]);
            c0[1] = ffma2(ww0, e1, c0[1]);
            c0[2] = ffma2(ww0, e2, c0[2]);
            c0[3] = ffma2(ww0, e3, c0[3]);
            c1[0] = ffma2(ww1, e0, c1[0]);
            c1[1] = ffma2(ww1, e1, c1[1]);
            c1[2] = ffma2(ww1, e2, c1[2]);
            c1[3] = ffma2(ww1, e3, c1[3]);
        }
    }

    // ---- exchange m-partials, store context ----
    float4 c0a, c0b, c1a, c1b;
    upk2(c0[0], c0a.x, c0a.y); upk2(c0[1], c0a.z, c0a.w);
    upk2(c0[2], c0b.x, c0b.y); upk2(c0[3], c0b.z, c0b.w);
    upk2(c1[0], c1a.x, c1a.y); upk2(c1[1], c1a.z, c1a.w);
    upk2(c1[2], c1b.x, c1b.y); upk2(c1[3], c1b.z, c1b.w);

    if (h == 1) {
        float4* p0 = (float4*)(sP + r0 * 256);
        float4* p1 = (float4*)(sP + r1 * 256);
        p0[lane]      = c0a;
        p0[32 + lane] = c0b;
        p1[lane]      = c1a;
        p1[32 + lane] = c1b;
    }
    __syncthreads();
    if (h == 0) {
        float4 q;
        q = ((float4*)(sP + r0 * 256))[lane];
        c0a.x += q.x; c0a.y += q.y; c0a.z += q.z; c0a.w += q.w;
        q = ((float4*)(sP + r0 * 256))[32 + lane];
        c0b.x += q.x; c0b.y += q.y; c0b.z += q.z; c0b.w += q.w;
        q = ((float4*)(sP + r1 * 256))[lane];
        c1a.x += q.x; c1a.y += q.y; c1a.z += q.z; c1a.w += q.w;
        q = ((float4*)(sP + r1 * 256))[32 + lane];
        c1b.x += q.x; c1b.y += q.y; c1b.z += q.z; c1b.w += q.w;

        float4* o0 = (float4*)(out_ctx + (size_t)(b * NN + gn0) * DD);
        o0[lane]      = c0a;
        o0[32 + lane] = c0b;
        float4* o1 = (float4*)(out_ctx + (size_t)(b * NN + gn1) * DD);
        o1[lane]      = c1a;
        o1[32 + lane] = c1b;
    }
    #undef PREFETCH
}

extern "C" void kernel_launch(void* const* d_in, const int* in_sizes, int n_in,
                              void* d_out, int out_size)
{
    const float* enc = (const float*)d_in[0];
    const float* dec = (const float*)d_in[1];
    const float* W1  = (const float*)d_in[2];
    const float* b1  = (const float*)d_in[3];
    const float* W2  = (const float*)d_in[4];
    const float* b2  = (const float*)d_in[5];
    const float* vw  = (const float*)d_in[6];
    // d_in[7] = v_b: constant shift, cancels in softmax -> unused.

    float* out_ctx = (float*)d_out;                              // [B,N,D]
    float* out_w   = (float*)d_out + (size_t)Bx * NN * DD;       // [B,N,M,1]

    proj_gemm<<<dim3(2, 32, 2), 256>>>(enc, dec, W1, b1, W2, b2);
    attn_kernel<<<512, 256>>>(enc, vw, out_ctx, out_w);
}